// round 3
// baseline (speedup 1.0000x reference)
#include <cuda_runtime.h>

// YoloLoss: N=4096, S=14, B=2, NUM_CLS=20 — single fused kernel.
// inputs: pred_tensor (N,S,S,30) f32, target_boxes (N,S,S,4) f32,
//         target_cls (N,S,S,20) f32, has_object_map (N,S,S) int32
// output: 5 f32 = (total, reg, contain_conf, no_obj, cls)

static constexpr int NSAMP = 4096;
static constexpr int S2    = 14 * 14;
static constexpr int NCELL = NSAMP * S2;   // 802816
static constexpr int CPB   = 128;          // cells (== threads) per block
static constexpr int NBLK  = NCELL / CPB;  // 6272

// global accumulators: reg_sum, contain_sum, noobj_sum(raw), cls_sum
// zero-initialized at load; last block resets them each run -> replay-safe.
__device__ float    g_acc[4];
__device__ unsigned g_count;

__global__ __launch_bounds__(CPB) void yolo_k(
    const float* __restrict__ pred,
    const float* __restrict__ tbox,
    const float* __restrict__ tcls,
    const int* __restrict__ mask,
    float* __restrict__ out)
{
    // padded smem: stride 31 / 21 odd -> conflict-free strided reads
    __shared__ float sp[CPB * 31];
    __shared__ float sc[CPB * 21];
    __shared__ float red[CPB / 32][4];
    __shared__ bool  is_last;

    const int tid = threadIdx.x;
    const long base = (long)blockIdx.x * CPB;

    // --- coalesced staging: pred (30 ch/cell) and cls (20 ch/cell) ---
    const float* __restrict__ pg = pred + base * 30;
    const float* __restrict__ cg = tcls + base * 20;
#pragma unroll
    for (int i = 0; i < 30; i++) {
        int idx  = tid + i * CPB;
        int cell = idx / 30;
        int ch   = idx - cell * 30;
        sp[cell * 31 + ch] = pg[idx];
    }
#pragma unroll
    for (int i = 0; i < 20; i++) {
        int idx  = tid + i * CPB;
        int cell = idx / 20;
        int ch   = idx - cell * 20;
        sc[cell * 21 + ch] = cg[idx];
    }
    __syncthreads();

    const long cell = base + tid;
    const float4 tb = reinterpret_cast<const float4*>(tbox)[cell]; // x,y,w,h
    const float  m  = (mask[cell] != 0) ? 1.0f : 0.0f;

    const float* P = &sp[tid * 31];
    const float* C = &sc[tid * 21];

    // classification loss
    float cls = 0.0f;
#pragma unroll
    for (int k = 0; k < 20; k++) {
        float d = P[10 + k] - C[k];
        cls += d * d;
    }
    cls *= m;

    // no-object confidence (raw; 0.5 applied at finalize)
    float c0 = P[4], c1 = P[9];
    float noobj = (c0 * c0 + c1 * c1) * (1.0f - m);

    // IoU vs target for both boxes
    const float invS = 1.0f / 14.0f;
    float gx1 = tb.x * invS - 0.5f * tb.z, gx2 = tb.x * invS + 0.5f * tb.z;
    float gy1 = tb.y * invS - 0.5f * tb.w, gy2 = tb.y * invS + 0.5f * tb.w;
    float area_g = (gx2 - gx1) * (gy2 - gy1);

    float iou0, iou1;
#pragma unroll
    for (int b = 0; b < 2; b++) {
        float px = P[5 * b + 0], py = P[5 * b + 1];
        float pw = P[5 * b + 2], ph = P[5 * b + 3];
        float px1 = px * invS - 0.5f * pw, px2 = px * invS + 0.5f * pw;
        float py1 = py * invS - 0.5f * ph, py2 = py * invS + 0.5f * ph;
        float iw = fmaxf(fminf(px2, gx2) - fmaxf(px1, gx1), 0.0f);
        float ih = fmaxf(fminf(py2, gy2) - fmaxf(py1, gy1), 0.0f);
        float inter  = iw * ih;
        float area_p = (px2 - px1) * (py2 - py1);
        float v = inter / (area_p + area_g - inter);
        if (b == 0) iou0 = v; else iou1 = v;
    }
    // jnp.argmax keeps first max on ties -> strict '>' to pick box 1
    const int best = (iou1 > iou0) ? 1 : 0;
    const float bx = P[5 * best + 0], by = P[5 * best + 1];
    const float bw = P[5 * best + 2], bh = P[5 * best + 3];
    const float bc = P[5 * best + 4];

    float dx = bx - tb.x, dy = by - tb.y;
    float dw = sqrtf(bw) - sqrtf(tb.z);
    float dh = sqrtf(bh) - sqrtf(tb.w);
    float regp = (dx * dx + dy * dy + dw * dw + dh * dh) * m; // L_COORD at finalize
    float dc = bc - 1.0f;
    float contain = dc * dc * m;

    // --- reduction: warp shuffle -> smem -> one thread does 4 atomics ---
    float v0 = regp, v1 = contain, v2 = noobj, v3 = cls;
#pragma unroll
    for (int off = 16; off > 0; off >>= 1) {
        v0 += __shfl_xor_sync(0xffffffffu, v0, off);
        v1 += __shfl_xor_sync(0xffffffffu, v1, off);
        v2 += __shfl_xor_sync(0xffffffffu, v2, off);
        v3 += __shfl_xor_sync(0xffffffffu, v3, off);
    }
    const int warp = tid >> 5;
    if ((tid & 31) == 0) {
        red[warp][0] = v0; red[warp][1] = v1;
        red[warp][2] = v2; red[warp][3] = v3;
    }
    __syncthreads();

    if (tid == 0) {
        float s0 = 0.f, s1 = 0.f, s2 = 0.f, s3 = 0.f;
#pragma unroll
        for (int w = 0; w < CPB / 32; w++) {
            s0 += red[w][0]; s1 += red[w][1];
            s2 += red[w][2]; s3 += red[w][3];
        }
        atomicAdd(&g_acc[0], s0);
        atomicAdd(&g_acc[1], s1);
        atomicAdd(&g_acc[2], s2);
        atomicAdd(&g_acc[3], s3);
        __threadfence();
        unsigned prev = atomicAdd(&g_count, 1u);
        is_last = (prev == (unsigned)(NBLK - 1));
    }
    __syncthreads();

    // last block finalizes and resets state for the next graph replay
    if (is_last && tid == 0) {
        __threadfence();  // acquire: all blocks' g_acc adds are visible
        const float invN = 1.0f / (float)NSAMP;
        float reg     = 5.0f * g_acc[0] * invN;
        float contain_t = g_acc[1] * invN;
        float noobj_t   = 0.5f * g_acc[2] * invN;
        float cls_t     = g_acc[3] * invN;
        out[0] = reg + contain_t + noobj_t + cls_t;
        out[1] = reg;
        out[2] = contain_t;
        out[3] = noobj_t;
        out[4] = cls_t;
        g_acc[0] = 0.0f; g_acc[1] = 0.0f;
        g_acc[2] = 0.0f; g_acc[3] = 0.0f;
        __threadfence();
        g_count = 0u;
    }
}

extern "C" void kernel_launch(void* const* d_in, const int* in_sizes, int n_in,
                              void* d_out, int out_size)
{
    const float* pred = (const float*)d_in[0];
    const float* tbox = (const float*)d_in[1];
    const float* tcls = (const float*)d_in[2];
    const int*   mask = (const int*)d_in[3];
    float* out = (float*)d_out;

    yolo_k<<<NBLK, CPB>>>(pred, tbox, tcls, mask, out);
}

// round 4
// speedup vs baseline: 1.3136x; 1.3136x over previous
#include <cuda_runtime.h>

// YoloLoss: N=4096, S=14, B=2, NUM_CLS=20 — main kernel + tiny finalize.
// inputs: pred_tensor (N,S,S,30) f32, target_boxes (N,S,S,4) f32,
//         target_cls (N,S,S,20) f32, has_object_map (N,S,S) int32
// output: 5 f32 = (total, reg, contain_conf, no_obj, cls)

static constexpr int NSAMP = 4096;
static constexpr int S2    = 14 * 14;
static constexpr int NCELL = NSAMP * S2;   // 802816
static constexpr int CPB   = 128;          // cells (== threads) per block
static constexpr int NBLK  = NCELL / CPB;  // 6272

// per-block partial sums: x=reg(raw), y=contain, z=noobj(raw), w=cls
// every slot is written every run -> no zeroing, no atomics, deterministic.
__device__ float4 g_part[NBLK];

__global__ __launch_bounds__(CPB, 12) void yolo_k(
    const float* __restrict__ pred,
    const float* __restrict__ tbox,
    const float* __restrict__ tcls,
    const int* __restrict__ mask)
{
    // pred staged at stride 31 (odd) -> conflict-free per-cell reads
    __shared__ float sp[CPB * 31];      // 15872 B
    __shared__ float smask[CPB];
    __shared__ float red[CPB / 32][4];

    const int tid = threadIdx.x;
    const long base = (long)blockIdx.x * CPB;

    // --- stage pred via float2 (30 even -> a pair never splits a cell) ---
    const float2* __restrict__ pg2 =
        reinterpret_cast<const float2*>(pred + base * 30);
#pragma unroll
    for (int i = 0; i < 15; i++) {
        int idx2 = tid + i * CPB;       // 0..1919
        float2 v = pg2[idx2];
        int e    = idx2 * 2;
        int cell = e / 30;
        int ch   = e - cell * 30;
        sp[cell * 31 + ch]     = v.x;
        sp[cell * 31 + ch + 1] = v.y;
    }
    smask[tid] = (mask[base + tid] != 0) ? 1.0f : 0.0f;
    __syncthreads();

    // --- cls loss fused into float4-streamed tcls (20%4==0: no cell split) ---
    const float4* __restrict__ cg4 =
        reinterpret_cast<const float4*>(tcls + base * 20);
    float cls = 0.0f;
#pragma unroll
    for (int i = 0; i < 5; i++) {
        int idx4 = tid + i * CPB;       // 0..639
        float4 v = cg4[idx4];
        int e    = idx4 * 4;
        int cell = e / 20;
        int ch   = e - cell * 20;       // in {0,4,8,12,16}
        const float* p = &sp[cell * 31 + 10 + ch];
        float d0 = p[0] - v.x, d1 = p[1] - v.y;
        float d2 = p[2] - v.z, d3 = p[3] - v.w;
        cls += (d0 * d0 + d1 * d1 + d2 * d2 + d3 * d3) * smask[cell];
    }

    // --- per-cell box terms ---
    const float4 tb = reinterpret_cast<const float4*>(tbox)[base + tid];
    const float  m  = smask[tid];
    const float* P  = &sp[tid * 31];

    float c0 = P[4], c1 = P[9];
    float noobj = (c0 * c0 + c1 * c1) * (1.0f - m);   // 0.5 at finalize

    const float invS = 1.0f / 14.0f;
    float gx1 = tb.x * invS - 0.5f * tb.z, gx2 = tb.x * invS + 0.5f * tb.z;
    float gy1 = tb.y * invS - 0.5f * tb.w, gy2 = tb.y * invS + 0.5f * tb.w;
    float area_g = (gx2 - gx1) * (gy2 - gy1);

    float iou0, iou1;
#pragma unroll
    for (int b = 0; b < 2; b++) {
        float px = P[5 * b + 0], py = P[5 * b + 1];
        float pw = P[5 * b + 2], ph = P[5 * b + 3];
        float px1 = px * invS - 0.5f * pw, px2 = px * invS + 0.5f * pw;
        float py1 = py * invS - 0.5f * ph, py2 = py * invS + 0.5f * ph;
        float iw = fmaxf(fminf(px2, gx2) - fmaxf(px1, gx1), 0.0f);
        float ih = fmaxf(fminf(py2, gy2) - fmaxf(py1, gy1), 0.0f);
        float inter  = iw * ih;
        float area_p = (px2 - px1) * (py2 - py1);
        float v = inter / (area_p + area_g - inter);
        if (b == 0) iou0 = v; else iou1 = v;
    }
    // jnp.argmax keeps first max on ties -> strict '>' for box 1
    const int best = (iou1 > iou0) ? 1 : 0;
    const float bx = P[5 * best + 0], by = P[5 * best + 1];
    const float bw = P[5 * best + 2], bh = P[5 * best + 3];
    const float bc = P[5 * best + 4];

    float dx = bx - tb.x, dy = by - tb.y;
    float dw = sqrtf(bw) - sqrtf(tb.z);
    float dh = sqrtf(bh) - sqrtf(tb.w);
    float regp = (dx * dx + dy * dy + dw * dw + dh * dh) * m; // L_COORD at finalize
    float dc = bc - 1.0f;
    float contain = dc * dc * m;

    // --- reduction: warp shuffle -> smem -> one STG.128 per block ---
    float v0 = regp, v1 = contain, v2 = noobj, v3 = cls;
#pragma unroll
    for (int off = 16; off > 0; off >>= 1) {
        v0 += __shfl_xor_sync(0xffffffffu, v0, off);
        v1 += __shfl_xor_sync(0xffffffffu, v1, off);
        v2 += __shfl_xor_sync(0xffffffffu, v2, off);
        v3 += __shfl_xor_sync(0xffffffffu, v3, off);
    }
    const int warp = tid >> 5;
    if ((tid & 31) == 0) {
        red[warp][0] = v0; red[warp][1] = v1;
        red[warp][2] = v2; red[warp][3] = v3;
    }
    __syncthreads();
    if (tid == 0) {
        float4 s = make_float4(0.f, 0.f, 0.f, 0.f);
#pragma unroll
        for (int w = 0; w < CPB / 32; w++) {
            s.x += red[w][0]; s.y += red[w][1];
            s.z += red[w][2]; s.w += red[w][3];
        }
        g_part[blockIdx.x] = s;
    }
}

__global__ __launch_bounds__(256) void finalize_k(float* __restrict__ out) {
    __shared__ float4 sred[256];
    const int t = threadIdx.x;
    float4 a = make_float4(0.f, 0.f, 0.f, 0.f);
    for (int b = t; b < NBLK; b += 256) {
        float4 p = g_part[b];
        a.x += p.x; a.y += p.y; a.z += p.z; a.w += p.w;
    }
    sred[t] = a;
    __syncthreads();
#pragma unroll
    for (int s = 128; s > 0; s >>= 1) {
        if (t < s) {
            float4 o = sred[t + s];
            a.x += o.x; a.y += o.y; a.z += o.z; a.w += o.w;
            sred[t] = a;
        }
        __syncthreads();
    }
    if (t == 0) {
        const float invN = 1.0f / (float)NSAMP;
        float reg     = 5.0f * a.x * invN;
        float contain = a.y * invN;
        float noobj   = 0.5f * a.z * invN;
        float cls     = a.w * invN;
        out[0] = reg + contain + noobj + cls;
        out[1] = reg;
        out[2] = contain;
        out[3] = noobj;
        out[4] = cls;
    }
}

extern "C" void kernel_launch(void* const* d_in, const int* in_sizes, int n_in,
                              void* d_out, int out_size)
{
    const float* pred = (const float*)d_in[0];
    const float* tbox = (const float*)d_in[1];
    const float* tcls = (const float*)d_in[2];
    const int*   mask = (const int*)d_in[3];
    float* out = (float*)d_out;

    yolo_k<<<NBLK, CPB>>>(pred, tbox, tcls, mask);
    finalize_k<<<1, 256>>>(out);
}